// round 1
// baseline (speedup 1.0000x reference)
#include <cuda_runtime.h>
#include <math.h>

#define NROWS 4096
#define DIM   1024
#define TEMP_INV 20.0f
#define EPS 1e-8f

// Normalized copies (allocation-free scratch: __device__ globals)
__device__ float g_xn[NROWS * DIM];
__device__ float g_yn[NROWS * DIM];

// ---------------------------------------------------------------------------
// Kernel 1: row L2-normalize x and y into g_xn / g_yn.
// One block per row; 256 threads * float4 = 1024 elements exactly.
// ---------------------------------------------------------------------------
__global__ __launch_bounds__(256) void normalize_kernel(
    const float* __restrict__ x, const float* __restrict__ y) {
    int row = blockIdx.x;
    const float* src;
    float* dst;
    if (row < NROWS) {
        src = x + (size_t)row * DIM;
        dst = g_xn + (size_t)row * DIM;
    } else {
        src = y + (size_t)(row - NROWS) * DIM;
        dst = g_yn + (size_t)(row - NROWS) * DIM;
    }
    int tid = threadIdx.x;
    float4 v = ((const float4*)src)[tid];
    float s = v.x * v.x + v.y * v.y + v.z * v.z + v.w * v.w;

    __shared__ float red[8];
    #pragma unroll
    for (int o = 16; o; o >>= 1) s += __shfl_down_sync(0xffffffffu, s, o);
    if ((tid & 31) == 0) red[tid >> 5] = s;
    __syncthreads();
    if (tid < 8) {
        float t = red[tid];
        #pragma unroll
        for (int o = 4; o; o >>= 1) t += __shfl_down_sync(0xffu, t, o);
        if (tid == 0) red[0] = t;
    }
    __syncthreads();
    float inv = 1.0f / fmaxf(sqrtf(red[0]), EPS);

    float4 o4 = make_float4(v.x * inv, v.y * inv, v.z * inv, v.w * inv);
    ((float4*)dst)[tid] = o4;
}

// ---------------------------------------------------------------------------
// Kernel 2: C[n][m] = (xn[n] . yn[m]) * 20
// Classic 128x128x8 SIMT SGEMM, 256 threads, 8x8 per-thread microtile.
// A = g_xn (row-major [4096,1024]), B = g_yn (row-major [4096,1024]),
// effectively C = A * B^T, which with both row-major over K means both
// tiles load identically (K contiguous) -> perfectly coalesced float4.
// ---------------------------------------------------------------------------
#define BM 128
#define BN 128
#define BK 8
#define TM 8
#define TN 8

__global__ __launch_bounds__(256) void gemm_kernel(float* __restrict__ C) {
    __shared__ float As[BK][BM];
    __shared__ float Bs[BK][BN];

    const int bx = blockIdx.x;  // N (y rows) tile
    const int by = blockIdx.y;  // M (x rows) tile

    const float* __restrict__ A = g_xn + (size_t)by * BM * DIM;
    const float* __restrict__ B = g_yn + (size_t)bx * BN * DIM;

    const int tid  = threadIdx.x;
    // global-load mapping: 128 rows x 8 K-cols per tile = 256 float4
    const int lrow  = tid >> 1;         // 0..127
    const int lcol4 = (tid & 1) << 2;   // 0 or 4

    // compute mapping: 16x16 threads, each owning 8x8 of C
    const int tcol = tid & 15;   // N direction
    const int trow = tid >> 4;   // M direction

    float acc[TM][TN] = {};
    float ar[TM], br[TN];

    for (int k0 = 0; k0 < DIM; k0 += BK) {
        float4 av = *(const float4*)(A + (size_t)lrow * DIM + k0 + lcol4);
        float4 bv = *(const float4*)(B + (size_t)lrow * DIM + k0 + lcol4);
        // store transposed: smem[k][row]
        As[lcol4 + 0][lrow] = av.x;
        As[lcol4 + 1][lrow] = av.y;
        As[lcol4 + 2][lrow] = av.z;
        As[lcol4 + 3][lrow] = av.w;
        Bs[lcol4 + 0][lrow] = bv.x;
        Bs[lcol4 + 1][lrow] = bv.y;
        Bs[lcol4 + 2][lrow] = bv.z;
        Bs[lcol4 + 3][lrow] = bv.w;
        __syncthreads();

        #pragma unroll
        for (int k = 0; k < BK; k++) {
            #pragma unroll
            for (int i = 0; i < TM; i += 4) {
                float4 t = *(const float4*)&As[k][trow * TM + i];
                ar[i] = t.x; ar[i + 1] = t.y; ar[i + 2] = t.z; ar[i + 3] = t.w;
            }
            #pragma unroll
            for (int j = 0; j < TN; j += 4) {
                float4 t = *(const float4*)&Bs[k][tcol * TN + j];
                br[j] = t.x; br[j + 1] = t.y; br[j + 2] = t.z; br[j + 3] = t.w;
            }
            #pragma unroll
            for (int i = 0; i < TM; i++)
                #pragma unroll
                for (int j = 0; j < TN; j++)
                    acc[i][j] += ar[i] * br[j];
        }
        __syncthreads();
    }

    // epilogue: scale by 1/TEMP, vectorized stores
    #pragma unroll
    for (int i = 0; i < TM; i++) {
        int row = by * BM + trow * TM + i;
        float4* cp = (float4*)(C + (size_t)row * NROWS + bx * BN + tcol * TN);
        cp[0] = make_float4(acc[i][0] * TEMP_INV, acc[i][1] * TEMP_INV,
                            acc[i][2] * TEMP_INV, acc[i][3] * TEMP_INV);
        cp[1] = make_float4(acc[i][4] * TEMP_INV, acc[i][5] * TEMP_INV,
                            acc[i][6] * TEMP_INV, acc[i][7] * TEMP_INV);
    }
}

extern "C" void kernel_launch(void* const* d_in, const int* in_sizes, int n_in,
                              void* d_out, int out_size) {
    const float* x = (const float*)d_in[0];
    const float* y = (const float*)d_in[1];
    float* out = (float*)d_out;

    normalize_kernel<<<2 * NROWS, 256>>>(x, y);

    dim3 grid(NROWS / BN, NROWS / BM);
    gemm_kernel<<<grid, 256>>>(out);
}

// round 3
// speedup vs baseline: 2.4538x; 2.4538x over previous
#include <cuda_runtime.h>
#include <cuda_bf16.h>
#include <cstdint>
#include <math.h>

#define NROWS 4096
#define DIM   1024
#define TEMP_INV 20.0f
#define EPS 1e-8f

#define BM 128
#define BN 128
#define BK 32
#define NKT (DIM / BK)        // 32 k-tiles
#define ROWB 80               // padded smem row stride in bytes (32 bf16 + 8 pad)
#define MAT_BYTES (128 * ROWB)        // 10240 per matrix per stage
#define OFF_AH 0
#define OFF_AL (1 * MAT_BYTES)
#define OFF_BH (2 * MAT_BYTES)
#define OFF_BL (3 * MAT_BYTES)
#define STAGE  (4 * MAT_BYTES)        // 40960
#define NSTG   3
#define SMEM_TOTAL (NSTG * STAGE)     // 122880

// bf16 hi/lo split of normalized inputs (allocation-free scratch)
__device__ __nv_bfloat16 g_xhi[NROWS * DIM];
__device__ __nv_bfloat16 g_xlo[NROWS * DIM];
__device__ __nv_bfloat16 g_yhi[NROWS * DIM];
__device__ __nv_bfloat16 g_ylo[NROWS * DIM];

// ---------------------------------------------------------------------------
// helpers
// ---------------------------------------------------------------------------
__device__ __forceinline__ uint32_t smem_to_u32(const void* p) {
    uint32_t a;
    asm("{ .reg .u64 t; cvta.to.shared.u64 t, %1; cvt.u32.u64 %0, t; }"
        : "=r"(a) : "l"(p));
    return a;
}

__device__ __forceinline__ void cp_async16(uint32_t s, const void* g) {
    asm volatile("cp.async.cg.shared.global [%0], [%1], 16;" :: "r"(s), "l"(g));
}

__device__ __forceinline__ void ldsm_x4(uint32_t& r0, uint32_t& r1,
                                        uint32_t& r2, uint32_t& r3, uint32_t addr) {
    asm volatile("ldmatrix.sync.aligned.m8n8.x4.shared.b16 {%0,%1,%2,%3}, [%4];"
                 : "=r"(r0), "=r"(r1), "=r"(r2), "=r"(r3) : "r"(addr));
}

__device__ __forceinline__ void mma16816(float* d, const uint32_t* a,
                                         uint32_t b0, uint32_t b1) {
    asm volatile(
        "mma.sync.aligned.m16n8k16.row.col.f32.bf16.bf16.f32 "
        "{%0,%1,%2,%3}, {%4,%5,%6,%7}, {%8,%9}, {%0,%1,%2,%3};"
        : "+f"(d[0]), "+f"(d[1]), "+f"(d[2]), "+f"(d[3])
        : "r"(a[0]), "r"(a[1]), "r"(a[2]), "r"(a[3]), "r"(b0), "r"(b1));
}

// ---------------------------------------------------------------------------
// Kernel 1: normalize rows, emit bf16 hi/lo split.
// ---------------------------------------------------------------------------
__global__ __launch_bounds__(256) void normalize_kernel(
    const float* __restrict__ x, const float* __restrict__ y) {
    int row = blockIdx.x;
    const float* src;
    __nv_bfloat16 *dhi, *dlo;
    if (row < NROWS) {
        src = x + (size_t)row * DIM;
        dhi = g_xhi + (size_t)row * DIM;
        dlo = g_xlo + (size_t)row * DIM;
    } else {
        src = y + (size_t)(row - NROWS) * DIM;
        dhi = g_yhi + (size_t)(row - NROWS) * DIM;
        dlo = g_ylo + (size_t)(row - NROWS) * DIM;
    }
    int tid = threadIdx.x;
    float4 v = ((const float4*)src)[tid];
    float s = v.x * v.x + v.y * v.y + v.z * v.z + v.w * v.w;

    __shared__ float red[8];
    #pragma unroll
    for (int o = 16; o; o >>= 1) s += __shfl_down_sync(0xffffffffu, s, o);
    if ((tid & 31) == 0) red[tid >> 5] = s;
    __syncthreads();
    if (tid < 8) {
        float t = red[tid];
        #pragma unroll
        for (int o = 4; o; o >>= 1) t += __shfl_down_sync(0xffu, t, o);
        if (tid == 0) red[0] = t;
    }
    __syncthreads();
    float inv = 1.0f / fmaxf(sqrtf(red[0]), EPS);

    float n[4] = {v.x * inv, v.y * inv, v.z * inv, v.w * inv};
    __nv_bfloat16 h[4], l[4];
    #pragma unroll
    for (int i = 0; i < 4; i++) {
        h[i] = __float2bfloat16(n[i]);
        l[i] = __float2bfloat16(n[i] - __bfloat162float(h[i]));
    }
    __nv_bfloat162 hp0 = __halves2bfloat162(h[0], h[1]);
    __nv_bfloat162 hp1 = __halves2bfloat162(h[2], h[3]);
    __nv_bfloat162 lp0 = __halves2bfloat162(l[0], l[1]);
    __nv_bfloat162 lp1 = __halves2bfloat162(l[2], l[3]);
    ((uint2*)dhi)[tid] = make_uint2(*(uint32_t*)&hp0, *(uint32_t*)&hp1);
    ((uint2*)dlo)[tid] = make_uint2(*(uint32_t*)&lp0, *(uint32_t*)&lp1);
}

// ---------------------------------------------------------------------------
// Kernel 2: HMMA bf16 hi/lo GEMM. C[n][m] = 20 * (xn[n] . yn[m])
// 128x128 CTA tile, BK=32, 3-stage cp.async pipeline, 8 warps (2x4),
// warp tile 64x32, mma.m16n8k16, fp32 accum.
// ---------------------------------------------------------------------------
__global__ __launch_bounds__(256, 1) void gemm_hmma(float* __restrict__ C) {
    extern __shared__ __align__(128) char smem[];
    const int tid = threadIdx.x;
    const int lane = tid & 31;
    const int wid = tid >> 5;
    const int wm = wid >> 2;       // 0..1  (M)
    const int wn = wid & 3;        // 0..3  (N)
    const int bx = blockIdx.x;     // N tile
    const int by = blockIdx.y;     // M tile

    const uint32_t sbase = smem_to_u32(smem);

    const __nv_bfloat16* __restrict__ Ah = g_xhi + (size_t)(by * BM) * DIM;
    const __nv_bfloat16* __restrict__ Al = g_xlo + (size_t)(by * BM) * DIM;
    const __nv_bfloat16* __restrict__ Bh = g_yhi + (size_t)(bx * BN) * DIM;
    const __nv_bfloat16* __restrict__ Bl = g_ylo + (size_t)(bx * BN) * DIM;

    // per-thread load mapping: 512 16B-chunks per matrix, 2 per thread
    const int c0row = tid >> 2;          // rows 0..63 for i=0, 64..127 for i=1
    const int c0ch  = tid & 3;

    auto load_stage = [&](int sidx, int kt) {
        const uint32_t sb = sbase + sidx * STAGE;
        const int k0 = kt * BK;
        #pragma unroll
        for (int i = 0; i < 2; i++) {
            int row = c0row + i * 64;
            uint32_t so = row * ROWB + c0ch * 16;
            size_t go = (size_t)row * DIM + k0 + c0ch * 8;
            cp_async16(sb + OFF_AH + so, Ah + go);
            cp_async16(sb + OFF_AL + so, Al + go);
            cp_async16(sb + OFF_BH + so, Bh + go);
            cp_async16(sb + OFF_BL + so, Bl + go);
        }
        asm volatile("cp.async.commit_group;" ::: "memory");
    };

    float acc[4][4][4];
    #pragma unroll
    for (int i = 0; i < 4; i++)
        #pragma unroll
        for (int j = 0; j < 4; j++)
            #pragma unroll
            for (int k = 0; k < 4; k++) acc[i][j][k] = 0.0f;

    load_stage(0, 0);
    load_stage(1, 1);

    // ldmatrix base offsets (within a stage/matrix)
    const int arow = wm * 64 + (lane & 15);   // + mi*16
    const int brow = wn * 32 + (lane & 15);   // + nj*16
    const int cshift = (lane >> 4) * 16;      // 0 or 16 bytes (8 bf16)

    for (int kt = 0; kt < NKT; kt++) {
        if (kt < NKT - 2)
            asm volatile("cp.async.wait_group 1;" ::: "memory");
        else
            asm volatile("cp.async.wait_group 0;" ::: "memory");
        __syncthreads();

        if (kt + 2 < NKT) load_stage((kt + 2) % NSTG, kt + 2);

        const uint32_t sb = sbase + (kt % NSTG) * STAGE;
        const uint32_t sAh = sb + OFF_AH;
        const uint32_t sAl = sb + OFF_AL;
        const uint32_t sBh = sb + OFF_BH;
        const uint32_t sBl = sb + OFF_BL;

        #pragma unroll
        for (int ks = 0; ks < 2; ks++) {
            const int colb = ks * 32 + cshift;

            uint32_t ah[4][4], al[4][4];
            #pragma unroll
            for (int mi = 0; mi < 4; mi++) {
                uint32_t ro = (arow + mi * 16) * ROWB + colb;
                ldsm_x4(ah[mi][0], ah[mi][1], ah[mi][2], ah[mi][3], sAh + ro);
                ldsm_x4(al[mi][0], al[mi][1], al[mi][2], al[mi][3], sAl + ro);
            }
            uint32_t bh[2][4], bl[2][4];
            #pragma unroll
            for (int nj = 0; nj < 2; nj++) {
                uint32_t ro = (brow + nj * 16) * ROWB + colb;
                ldsm_x4(bh[nj][0], bh[nj][1], bh[nj][2], bh[nj][3], sBh + ro);
                ldsm_x4(bl[nj][0], bl[nj][1], bl[nj][2], bl[nj][3], sBl + ro);
            }

            #pragma unroll
            for (int mi = 0; mi < 4; mi++) {
                #pragma unroll
                for (int nt = 0; nt < 4; nt++) {
                    const int nj = nt >> 1, h = nt & 1;
                    mma16816(acc[mi][nt], ah[mi], bh[nj][h], bh[nj][h + 2]);
                    mma16816(acc[mi][nt], ah[mi], bl[nj][h], bl[nj][h + 2]);
                    mma16816(acc[mi][nt], al[mi], bh[nj][h], bh[nj][h + 2]);
                }
            }
        }
        __syncthreads();
    }

    // epilogue: scale by 20, direct float2 stores
    const int erow = by * BM + wm * 64 + (lane >> 2);
    const int ecol = bx * BN + wn * 32 + (lane & 3) * 2;
    #pragma unroll
    for (int mi = 0; mi < 4; mi++) {
        #pragma unroll
        for (int nt = 0; nt < 4; nt++) {
            float* p0 = C + (size_t)(erow + mi * 16) * NROWS + ecol + nt * 8;
            float* p1 = p0 + 8 * NROWS;
            *(float2*)p0 = make_float2(acc[mi][nt][0] * TEMP_INV,
                                       acc[mi][nt][1] * TEMP_INV);
            *(float2*)p1 = make_float2(acc[mi][nt][2] * TEMP_INV,
                                       acc[mi][nt][3] * TEMP_INV);
        }
    }
}

extern "C" void kernel_launch(void* const* d_in, const int* in_sizes, int n_in,
                              void* d_out, int out_size) {
    const float* x = (const float*)d_in[0];
    const float* y = (const float*)d_in[1];
    float* out = (float*)d_out;

    normalize_kernel<<<2 * NROWS, 256>>>(x, y);

    cudaFuncSetAttribute(gemm_hmma,
                         cudaFuncAttributeMaxDynamicSharedMemorySize, SMEM_TOTAL);
    dim3 grid(NROWS / BN, NROWS / BM);
    gemm_hmma<<<grid, 256, SMEM_TOTAL>>>(out);
}

// round 4
// speedup vs baseline: 2.7539x; 1.1223x over previous
#include <cuda_runtime.h>
#include <cuda_bf16.h>
#include <cstdint>
#include <math.h>

#define NROWS 4096
#define DIM   1024
#define TEMP_INV 20.0f
#define EPS 1e-8f

#define BM 128
#define BN 128
#define BK 32
#define NKT (DIM / BK)        // 32 k-tiles
#define ROWB 80               // padded smem row stride in bytes (32 bf16 + 8 pad)
#define MAT_BYTES (128 * ROWB)        // 10240 per matrix per stage
#define OFF_AH 0
#define OFF_AL (1 * MAT_BYTES)
#define OFF_BH (2 * MAT_BYTES)
#define OFF_BL (3 * MAT_BYTES)
#define STAGE  (4 * MAT_BYTES)        // 40960
#define NSTG   2
#define SMEM_TOTAL (NSTG * STAGE)     // 81920 -> 2 CTAs/SM

// bf16 hi/lo split of normalized inputs (allocation-free scratch)
__device__ __nv_bfloat16 g_xhi[NROWS * DIM];
__device__ __nv_bfloat16 g_xlo[NROWS * DIM];
__device__ __nv_bfloat16 g_yhi[NROWS * DIM];
__device__ __nv_bfloat16 g_ylo[NROWS * DIM];

// ---------------------------------------------------------------------------
// helpers
// ---------------------------------------------------------------------------
__device__ __forceinline__ uint32_t smem_to_u32(const void* p) {
    uint32_t a;
    asm("{ .reg .u64 t; cvta.to.shared.u64 t, %1; cvt.u32.u64 %0, t; }"
        : "=r"(a) : "l"(p));
    return a;
}

__device__ __forceinline__ void cp_async16(uint32_t s, const void* g) {
    asm volatile("cp.async.cg.shared.global [%0], [%1], 16;" :: "r"(s), "l"(g));
}

__device__ __forceinline__ void ldsm_x4(uint32_t& r0, uint32_t& r1,
                                        uint32_t& r2, uint32_t& r3, uint32_t addr) {
    asm volatile("ldmatrix.sync.aligned.m8n8.x4.shared.b16 {%0,%1,%2,%3}, [%4];"
                 : "=r"(r0), "=r"(r1), "=r"(r2), "=r"(r3) : "r"(addr));
}

__device__ __forceinline__ void mma16816(float* d, const uint32_t* a,
                                         uint32_t b0, uint32_t b1) {
    asm volatile(
        "mma.sync.aligned.m16n8k16.row.col.f32.bf16.bf16.f32 "
        "{%0,%1,%2,%3}, {%4,%5,%6,%7}, {%8,%9}, {%0,%1,%2,%3};"
        : "+f"(d[0]), "+f"(d[1]), "+f"(d[2]), "+f"(d[3])
        : "r"(a[0]), "r"(a[1]), "r"(a[2]), "r"(a[3]), "r"(b0), "r"(b1));
}

// ---------------------------------------------------------------------------
// Kernel 1: normalize rows, emit bf16 hi/lo split.
// ---------------------------------------------------------------------------
__global__ __launch_bounds__(256) void normalize_kernel(
    const float* __restrict__ x, const float* __restrict__ y) {
    int row = blockIdx.x;
    const float* src;
    __nv_bfloat16 *dhi, *dlo;
    if (row < NROWS) {
        src = x + (size_t)row * DIM;
        dhi = g_xhi + (size_t)row * DIM;
        dlo = g_xlo + (size_t)row * DIM;
    } else {
        src = y + (size_t)(row - NROWS) * DIM;
        dhi = g_yhi + (size_t)(row - NROWS) * DIM;
        dlo = g_ylo + (size_t)(row - NROWS) * DIM;
    }
    int tid = threadIdx.x;
    float4 v = ((const float4*)src)[tid];
    float s = v.x * v.x + v.y * v.y + v.z * v.z + v.w * v.w;

    __shared__ float red[8];
    #pragma unroll
    for (int o = 16; o; o >>= 1) s += __shfl_down_sync(0xffffffffu, s, o);
    if ((tid & 31) == 0) red[tid >> 5] = s;
    __syncthreads();
    if (tid < 8) {
        float t = red[tid];
        #pragma unroll
        for (int o = 4; o; o >>= 1) t += __shfl_down_sync(0xffu, t, o);
        if (tid == 0) red[0] = t;
    }
    __syncthreads();
    float inv = 1.0f / fmaxf(sqrtf(red[0]), EPS);

    float n[4] = {v.x * inv, v.y * inv, v.z * inv, v.w * inv};
    __nv_bfloat16 h[4], l[4];
    #pragma unroll
    for (int i = 0; i < 4; i++) {
        h[i] = __float2bfloat16(n[i]);
        l[i] = __float2bfloat16(n[i] - __bfloat162float(h[i]));
    }
    __nv_bfloat162 hp0 = __halves2bfloat162(h[0], h[1]);
    __nv_bfloat162 hp1 = __halves2bfloat162(h[2], h[3]);
    __nv_bfloat162 lp0 = __halves2bfloat162(l[0], l[1]);
    __nv_bfloat162 lp1 = __halves2bfloat162(l[2], l[3]);
    ((uint2*)dhi)[tid] = make_uint2(*(uint32_t*)&hp0, *(uint32_t*)&hp1);
    ((uint2*)dlo)[tid] = make_uint2(*(uint32_t*)&lp0, *(uint32_t*)&lp1);
}

// ---------------------------------------------------------------------------
// Kernel 2: HMMA bf16 hi/lo GEMM. C[n][m] = 20 * (xn[n] . yn[m])
// 128x128 CTA tile, BK=32, 2-stage cp.async pipeline (2 CTAs/SM), 8 warps
// (2x4), warp tile 64x32, mma.m16n8k16, fp32 accum.
// ---------------------------------------------------------------------------
__global__ __launch_bounds__(256, 2) void gemm_hmma(float* __restrict__ C) {
    extern __shared__ __align__(128) char smem[];
    const int tid = threadIdx.x;
    const int lane = tid & 31;
    const int wid = tid >> 5;
    const int wm = wid >> 2;       // 0..1  (M)
    const int wn = wid & 3;        // 0..3  (N)
    const int bx = blockIdx.x;     // N tile
    const int by = blockIdx.y;     // M tile

    const uint32_t sbase = smem_to_u32(smem);

    const __nv_bfloat16* __restrict__ Ah = g_xhi + (size_t)(by * BM) * DIM;
    const __nv_bfloat16* __restrict__ Al = g_xlo + (size_t)(by * BM) * DIM;
    const __nv_bfloat16* __restrict__ Bh = g_yhi + (size_t)(bx * BN) * DIM;
    const __nv_bfloat16* __restrict__ Bl = g_ylo + (size_t)(bx * BN) * DIM;

    // per-thread load mapping: 512 16B-chunks per matrix, 2 per thread
    const int c0row = tid >> 2;          // rows 0..63 for i=0, 64..127 for i=1
    const int c0ch  = tid & 3;

    auto load_stage = [&](int sidx, int kt) {
        const uint32_t sb = sbase + sidx * STAGE;
        const int k0 = kt * BK;
        #pragma unroll
        for (int i = 0; i < 2; i++) {
            int row = c0row + i * 64;
            uint32_t so = row * ROWB + c0ch * 16;
            size_t go = (size_t)row * DIM + k0 + c0ch * 8;
            cp_async16(sb + OFF_AH + so, Ah + go);
            cp_async16(sb + OFF_AL + so, Al + go);
            cp_async16(sb + OFF_BH + so, Bh + go);
            cp_async16(sb + OFF_BL + so, Bl + go);
        }
        asm volatile("cp.async.commit_group;" ::: "memory");
    };

    float acc[4][4][4];
    #pragma unroll
    for (int i = 0; i < 4; i++)
        #pragma unroll
        for (int j = 0; j < 4; j++)
            #pragma unroll
            for (int k = 0; k < 4; k++) acc[i][j][k] = 0.0f;

    load_stage(0, 0);
    load_stage(1, 1);

    // ldmatrix base offsets (within a stage/matrix)
    const int arow = wm * 64 + (lane & 15);   // + mi*16
    const int brow = wn * 32 + (lane & 15);   // + nj*16
    const int cshift = (lane >> 4) * 16;      // 0 or 16 bytes (8 bf16)

    for (int kt = 0; kt < NKT; kt++) {
        if (kt + 1 < NKT)
            asm volatile("cp.async.wait_group 1;" ::: "memory");
        else
            asm volatile("cp.async.wait_group 0;" ::: "memory");
        __syncthreads();

        const uint32_t sb = sbase + (kt & 1) * STAGE;
        const uint32_t sAh = sb + OFF_AH;
        const uint32_t sAl = sb + OFF_AL;
        const uint32_t sBh = sb + OFF_BH;
        const uint32_t sBl = sb + OFF_BL;

        #pragma unroll
        for (int ks = 0; ks < 2; ks++) {
            const int colb = ks * 32 + cshift;

            uint32_t ah[4][4], al[4][4];
            #pragma unroll
            for (int mi = 0; mi < 4; mi++) {
                uint32_t ro = (arow + mi * 16) * ROWB + colb;
                ldsm_x4(ah[mi][0], ah[mi][1], ah[mi][2], ah[mi][3], sAh + ro);
                ldsm_x4(al[mi][0], al[mi][1], al[mi][2], al[mi][3], sAl + ro);
            }
            uint32_t bh[2][4], bl[2][4];
            #pragma unroll
            for (int nj = 0; nj < 2; nj++) {
                uint32_t ro = (brow + nj * 16) * ROWB + colb;
                ldsm_x4(bh[nj][0], bh[nj][1], bh[nj][2], bh[nj][3], sBh + ro);
                ldsm_x4(bl[nj][0], bl[nj][1], bl[nj][2], bl[nj][3], sBl + ro);
            }

            #pragma unroll
            for (int mi = 0; mi < 4; mi++) {
                #pragma unroll
                for (int nt = 0; nt < 4; nt++) {
                    const int nj = nt >> 1, h = nt & 1;
                    mma16816(acc[mi][nt], ah[mi], bh[nj][h], bh[nj][h + 2]);
                    mma16816(acc[mi][nt], ah[mi], bl[nj][h], bl[nj][h + 2]);
                    mma16816(acc[mi][nt], al[mi], bh[nj][h], bh[nj][h + 2]);
                }
            }
        }
        __syncthreads();

        // refill the buffer just consumed (its cp.async lands behind the
        // wait_group fence two iterations from now)
        if (kt + 2 < NKT) load_stage(kt & 1, kt + 2);
    }

    // epilogue: scale by 20, direct float2 stores
    const int erow = by * BM + wm * 64 + (lane >> 2);
    const int ecol = bx * BN + wn * 32 + (lane & 3) * 2;
    #pragma unroll
    for (int mi = 0; mi < 4; mi++) {
        #pragma unroll
        for (int nt = 0; nt < 4; nt++) {
            float* p0 = C + (size_t)(erow + mi * 16) * NROWS + ecol + nt * 8;
            float* p1 = p0 + 8 * NROWS;
            *(float2*)p0 = make_float2(acc[mi][nt][0] * TEMP_INV,
                                       acc[mi][nt][1] * TEMP_INV);
            *(float2*)p1 = make_float2(acc[mi][nt][2] * TEMP_INV,
                                       acc[mi][nt][3] * TEMP_INV);
        }
    }
}

extern "C" void kernel_launch(void* const* d_in, const int* in_sizes, int n_in,
                              void* d_out, int out_size) {
    const float* x = (const float*)d_in[0];
    const float* y = (const float*)d_in[1];
    float* out = (float*)d_out;

    normalize_kernel<<<2 * NROWS, 256>>>(x, y);

    cudaFuncSetAttribute(gemm_hmma,
                         cudaFuncAttributeMaxDynamicSharedMemorySize, SMEM_TOTAL);
    dim3 grid(NROWS / BN, NROWS / BM);
    gemm_hmma<<<grid, 256, SMEM_TOTAL>>>(out);
}

// round 5
// speedup vs baseline: 3.1787x; 1.1543x over previous
#include <cuda_runtime.h>
#include <cuda_bf16.h>
#include <cstdint>
#include <math.h>

#define NROWS 4096
#define DIM   1024
#define TEMP_INV 20.0f
#define EPS 1e-8f

#define BM 128
#define BN 128
#define BK 32
#define NKT (DIM / BK)        // 32 k-tiles
#define ROWB 64               // smem row stride in bytes (no pad; XOR swizzle)
#define MAT_BYTES (128 * ROWB)        // 8192 per matrix per stage
#define OFF_AH 0
#define OFF_AL (1 * MAT_BYTES)
#define OFF_BH (2 * MAT_BYTES)
#define OFF_BL (3 * MAT_BYTES)
#define STAGE  (4 * MAT_BYTES)        // 32768
#define NSTG   3
#define SMEM_TOTAL (NSTG * STAGE)     // 98304 -> 2 CTAs/SM

// swizzled byte offset within one matrix tile: row r (0..127), chunk c (0..3)
#define SWZ_OFF(r, c) ((r) * ROWB + (((c) ^ (((r) >> 1) & 3)) << 4))

// bf16 hi/lo split of normalized inputs (allocation-free scratch)
__device__ __nv_bfloat16 g_xhi[NROWS * DIM];
__device__ __nv_bfloat16 g_xlo[NROWS * DIM];
__device__ __nv_bfloat16 g_yhi[NROWS * DIM];
__device__ __nv_bfloat16 g_ylo[NROWS * DIM];

// ---------------------------------------------------------------------------
// helpers
// ---------------------------------------------------------------------------
__device__ __forceinline__ uint32_t smem_to_u32(const void* p) {
    uint32_t a;
    asm("{ .reg .u64 t; cvta.to.shared.u64 t, %1; cvt.u32.u64 %0, t; }"
        : "=r"(a) : "l"(p));
    return a;
}

__device__ __forceinline__ void cp_async16(uint32_t s, const void* g) {
    asm volatile("cp.async.cg.shared.global [%0], [%1], 16;" :: "r"(s), "l"(g));
}

__device__ __forceinline__ void ldsm_x4(uint32_t& r0, uint32_t& r1,
                                        uint32_t& r2, uint32_t& r3, uint32_t addr) {
    asm volatile("ldmatrix.sync.aligned.m8n8.x4.shared.b16 {%0,%1,%2,%3}, [%4];"
                 : "=r"(r0), "=r"(r1), "=r"(r2), "=r"(r3) : "r"(addr));
}

__device__ __forceinline__ void mma16816(float* d, const uint32_t* a,
                                         uint32_t b0, uint32_t b1) {
    asm volatile(
        "mma.sync.aligned.m16n8k16.row.col.f32.bf16.bf16.f32 "
        "{%0,%1,%2,%3}, {%4,%5,%6,%7}, {%8,%9}, {%0,%1,%2,%3};"
        : "+f"(d[0]), "+f"(d[1]), "+f"(d[2]), "+f"(d[3])
        : "r"(a[0]), "r"(a[1]), "r"(a[2]), "r"(a[3]), "r"(b0), "r"(b1));
}

// ---------------------------------------------------------------------------
// Kernel 1: normalize rows, emit bf16 hi/lo split.
// ---------------------------------------------------------------------------
__global__ __launch_bounds__(256) void normalize_kernel(
    const float* __restrict__ x, const float* __restrict__ y) {
    int row = blockIdx.x;
    const float* src;
    __nv_bfloat16 *dhi, *dlo;
    if (row < NROWS) {
        src = x + (size_t)row * DIM;
        dhi = g_xhi + (size_t)row * DIM;
        dlo = g_xlo + (size_t)row * DIM;
    } else {
        src = y + (size_t)(row - NROWS) * DIM;
        dhi = g_yhi + (size_t)(row - NROWS) * DIM;
        dlo = g_ylo + (size_t)(row - NROWS) * DIM;
    }
    int tid = threadIdx.x;
    float4 v = ((const float4*)src)[tid];
    float s = v.x * v.x + v.y * v.y + v.z * v.z + v.w * v.w;

    __shared__ float red[8];
    #pragma unroll
    for (int o = 16; o; o >>= 1) s += __shfl_down_sync(0xffffffffu, s, o);
    if ((tid & 31) == 0) red[tid >> 5] = s;
    __syncthreads();
    if (tid < 8) {
        float t = red[tid];
        #pragma unroll
        for (int o = 4; o; o >>= 1) t += __shfl_down_sync(0xffu, t, o);
        if (tid == 0) red[0] = t;
    }
    __syncthreads();
    float inv = 1.0f / fmaxf(sqrtf(red[0]), EPS);

    float n[4] = {v.x * inv, v.y * inv, v.z * inv, v.w * inv};
    __nv_bfloat16 h[4], l[4];
    #pragma unroll
    for (int i = 0; i < 4; i++) {
        h[i] = __float2bfloat16(n[i]);
        l[i] = __float2bfloat16(n[i] - __bfloat162float(h[i]));
    }
    __nv_bfloat162 hp0 = __halves2bfloat162(h[0], h[1]);
    __nv_bfloat162 hp1 = __halves2bfloat162(h[2], h[3]);
    __nv_bfloat162 lp0 = __halves2bfloat162(l[0], l[1]);
    __nv_bfloat162 lp1 = __halves2bfloat162(l[2], l[3]);
    ((uint2*)dhi)[tid] = make_uint2(*(uint32_t*)&hp0, *(uint32_t*)&hp1);
    ((uint2*)dlo)[tid] = make_uint2(*(uint32_t*)&lp0, *(uint32_t*)&lp1);
}

// ---------------------------------------------------------------------------
// Kernel 2: HMMA bf16 hi/lo GEMM. C[n][m] = 20 * (xn[n] . yn[m])
// 128x128 CTA tile, BK=32, 3-stage cp.async pipeline (one barrier per k-tile,
// 2 CTAs/SM), 8 warps (2x4), warp tile 64x32, mma.m16n8k16, fp32 accum.
// ---------------------------------------------------------------------------
__global__ __launch_bounds__(256, 2) void gemm_hmma(float* __restrict__ C) {
    extern __shared__ __align__(128) char smem[];
    const int tid = threadIdx.x;
    const int lane = tid & 31;
    const int wid = tid >> 5;
    const int wm = wid >> 2;       // 0..1  (M)
    const int wn = wid & 3;        // 0..3  (N)
    const int bx = blockIdx.x;     // N tile
    const int by = blockIdx.y;     // M tile

    const uint32_t sbase = smem_to_u32(smem);

    const __nv_bfloat16* __restrict__ Ah = g_xhi + (size_t)(by * BM) * DIM;
    const __nv_bfloat16* __restrict__ Al = g_xlo + (size_t)(by * BM) * DIM;
    const __nv_bfloat16* __restrict__ Bh = g_yhi + (size_t)(bx * BN) * DIM;
    const __nv_bfloat16* __restrict__ Bl = g_ylo + (size_t)(bx * BN) * DIM;

    // per-thread load mapping: 512 16B-chunks per matrix, 2 per thread
    const int c0row = tid >> 2;          // rows 0..63 (i=0), 64..127 (i=1)
    const int c0ch  = tid & 3;

    auto load_stage = [&](int sidx, int kt) {
        const uint32_t sb = sbase + sidx * STAGE;
        const int k0 = kt * BK;
        #pragma unroll
        for (int i = 0; i < 2; i++) {
            int row = c0row + i * 64;
            uint32_t so = SWZ_OFF(row, c0ch);
            size_t go = (size_t)row * DIM + k0 + c0ch * 8;
            cp_async16(sb + OFF_AH + so, Ah + go);
            cp_async16(sb + OFF_AL + so, Al + go);
            cp_async16(sb + OFF_BH + so, Bh + go);
            cp_async16(sb + OFF_BL + so, Bl + go);
        }
        asm volatile("cp.async.commit_group;" ::: "memory");
    };

    float acc[4][4][4];
    #pragma unroll
    for (int i = 0; i < 4; i++)
        #pragma unroll
        for (int j = 0; j < 4; j++)
            #pragma unroll
            for (int k = 0; k < 4; k++) acc[i][j][k] = 0.0f;

    load_stage(0, 0);
    load_stage(1, 1);

    // ldmatrix row/chunk mapping
    const int arow = wm * 64 + (lane & 15);   // + mi*16
    const int brow = wn * 32 + (lane & 15);   // + nj*16
    const int chi  = lane >> 4;               // 0 or 1 (16B chunk within 16 cols)

    for (int kt = 0; kt < NKT; kt++) {
        if (kt + 1 < NKT)
            asm volatile("cp.async.wait_group 1;" ::: "memory");
        else
            asm volatile("cp.async.wait_group 0;" ::: "memory");
        __syncthreads();

        // refill the buffer consumed at kt-1 (sync above makes it safe)
        if (kt + 2 < NKT) load_stage((kt + 2) % NSTG, kt + 2);

        const uint32_t sb = sbase + (kt % NSTG) * STAGE;
        const uint32_t sAh = sb + OFF_AH;
        const uint32_t sAl = sb + OFF_AL;
        const uint32_t sBh = sb + OFF_BH;
        const uint32_t sBl = sb + OFF_BL;

        #pragma unroll
        for (int ks = 0; ks < 2; ks++) {
            const int ch = ks * 2 + chi;     // chunk index 0..3

            uint32_t ah[4][4], al[4][4];
            #pragma unroll
            for (int mi = 0; mi < 4; mi++) {
                int r = arow + mi * 16;
                uint32_t ro = SWZ_OFF(r, ch);
                ldsm_x4(ah[mi][0], ah[mi][1], ah[mi][2], ah[mi][3], sAh + ro);
                ldsm_x4(al[mi][0], al[mi][1], al[mi][2], al[mi][3], sAl + ro);
            }
            uint32_t bh[2][4], bl[2][4];
            #pragma unroll
            for (int nj = 0; nj < 2; nj++) {
                int r = brow + nj * 16;
                uint32_t ro = SWZ_OFF(r, ch);
                ldsm_x4(bh[nj][0], bh[nj][1], bh[nj][2], bh[nj][3], sBh + ro);
                ldsm_x4(bl[nj][0], bl[nj][1], bl[nj][2], bl[nj][3], sBl + ro);
            }

            #pragma unroll
            for (int mi = 0; mi < 4; mi++) {
                #pragma unroll
                for (int nt = 0; nt < 4; nt++) {
                    const int nj = nt >> 1, h = nt & 1;
                    mma16816(acc[mi][nt], ah[mi], bh[nj][h], bh[nj][h + 2]);
                    mma16816(acc[mi][nt], ah[mi], bl[nj][h], bl[nj][h + 2]);
                    mma16816(acc[mi][nt], al[mi], bh[nj][h], bh[nj][h + 2]);
                }
            }
        }
    }

    // epilogue: scale by 20, direct float2 stores
    const int erow = by * BM + wm * 64 + (lane >> 2);
    const int ecol = bx * BN + wn * 32 + (lane & 3) * 2;
    #pragma unroll
    for (int mi = 0; mi < 4; mi++) {
        #pragma unroll
        for (int nt = 0; nt < 4; nt++) {
            float* p0 = C + (size_t)(erow + mi * 16) * NROWS + ecol + nt * 8;
            float* p1 = p0 + 8 * NROWS;
            *(float2*)p0 = make_float2(acc[mi][nt][0] * TEMP_INV,
                                       acc[mi][nt][1] * TEMP_INV);
            *(float2*)p1 = make_float2(acc[mi][nt][2] * TEMP_INV,
                                       acc[mi][nt][3] * TEMP_INV);
        }
    }
}

extern "C" void kernel_launch(void* const* d_in, const int* in_sizes, int n_in,
                              void* d_out, int out_size) {
    const float* x = (const float*)d_in[0];
    const float* y = (const float*)d_in[1];
    float* out = (float*)d_out;

    normalize_kernel<<<2 * NROWS, 256>>>(x, y);

    cudaFuncSetAttribute(gemm_hmma,
                         cudaFuncAttributeMaxDynamicSharedMemorySize, SMEM_TOTAL);
    dim3 grid(NROWS / BN, NROWS / BM);
    gemm_hmma<<<grid, 256, SMEM_TOTAL>>>(out);
}

// round 6
// speedup vs baseline: 7.7681x; 2.4438x over previous
#include <cuda_runtime.h>
#include <cuda_fp16.h>
#include <cstdint>
#include <math.h>

#define NROWS 4096
#define DIM   1024
#define TEMP_INV 20.0f
#define EPS 1e-8f

#define BM 128
#define BN 128
#define BK 32
#define NKT (DIM / BK)        // 32 k-tiles
#define ROWB 64               // smem row stride in bytes (XOR swizzle)
#define MAT_BYTES (128 * ROWB)        // 8192 per matrix per stage
#define OFF_A 0
#define OFF_B MAT_BYTES
#define STAGE  (2 * MAT_BYTES)        // 16384
#define NSTG   4
#define SMEM_TOTAL (NSTG * STAGE)     // 65536 -> 2 CTAs/SM

// swizzled byte offset within one matrix tile: row r (0..127), chunk c (0..3)
#define SWZ_OFF(r, c) ((r) * ROWB + (((c) ^ (((r) >> 1) & 3)) << 4))

// fp16 normalized inputs (allocation-free scratch)
__device__ __half g_xh[NROWS * DIM];
__device__ __half g_yh[NROWS * DIM];

// ---------------------------------------------------------------------------
// helpers
// ---------------------------------------------------------------------------
__device__ __forceinline__ uint32_t smem_to_u32(const void* p) {
    uint32_t a;
    asm("{ .reg .u64 t; cvta.to.shared.u64 t, %1; cvt.u32.u64 %0, t; }"
        : "=r"(a) : "l"(p));
    return a;
}

__device__ __forceinline__ void cp_async16(uint32_t s, const void* g) {
    asm volatile("cp.async.cg.shared.global [%0], [%1], 16;" :: "r"(s), "l"(g));
}

__device__ __forceinline__ void ldsm_x4(uint32_t& r0, uint32_t& r1,
                                        uint32_t& r2, uint32_t& r3, uint32_t addr) {
    asm volatile("ldmatrix.sync.aligned.m8n8.x4.shared.b16 {%0,%1,%2,%3}, [%4];"
                 : "=r"(r0), "=r"(r1), "=r"(r2), "=r"(r3) : "r"(addr));
}

__device__ __forceinline__ void mma16816(float* d, const uint32_t* a,
                                         uint32_t b0, uint32_t b1) {
    asm volatile(
        "mma.sync.aligned.m16n8k16.row.col.f32.f16.f16.f32 "
        "{%0,%1,%2,%3}, {%4,%5,%6,%7}, {%8,%9}, {%0,%1,%2,%3};"
        : "+f"(d[0]), "+f"(d[1]), "+f"(d[2]), "+f"(d[3])
        : "r"(a[0]), "r"(a[1]), "r"(a[2]), "r"(a[3]), "r"(b0), "r"(b1));
}

// ---------------------------------------------------------------------------
// Kernel 1: normalize rows, emit fp16.
// ---------------------------------------------------------------------------
__global__ __launch_bounds__(256) void normalize_kernel(
    const float* __restrict__ x, const float* __restrict__ y) {
    int row = blockIdx.x;
    const float* src;
    __half* dst;
    if (row < NROWS) {
        src = x + (size_t)row * DIM;
        dst = g_xh + (size_t)row * DIM;
    } else {
        src = y + (size_t)(row - NROWS) * DIM;
        dst = g_yh + (size_t)(row - NROWS) * DIM;
    }
    int tid = threadIdx.x;
    float4 v = ((const float4*)src)[tid];
    float s = v.x * v.x + v.y * v.y + v.z * v.z + v.w * v.w;

    __shared__ float red[8];
    #pragma unroll
    for (int o = 16; o; o >>= 1) s += __shfl_down_sync(0xffffffffu, s, o);
    if ((tid & 31) == 0) red[tid >> 5] = s;
    __syncthreads();
    if (tid < 8) {
        float t = red[tid];
        #pragma unroll
        for (int o = 4; o; o >>= 1) t += __shfl_down_sync(0xffu, t, o);
        if (tid == 0) red[0] = t;
    }
    __syncthreads();
    float inv = 1.0f / fmaxf(sqrtf(red[0]), EPS);

    __half2 p0 = __floats2half2_rn(v.x * inv, v.y * inv);
    __half2 p1 = __floats2half2_rn(v.z * inv, v.w * inv);
    ((uint2*)dst)[tid] = make_uint2(*(uint32_t*)&p0, *(uint32_t*)&p1);
}

// ---------------------------------------------------------------------------
// Kernel 2: fp16 HMMA GEMM. C[n][m] = 20 * (xn[n] . yn[m])
// 128x128 CTA tile, BK=32, 4-stage cp.async pipeline (one barrier per k-tile,
// 2 CTAs/SM), 8 warps (2x4), warp tile 64x32, mma.m16n8k16.f16, fp32 accum.
// ---------------------------------------------------------------------------
__global__ __launch_bounds__(256, 2) void gemm_hmma(float* __restrict__ C) {
    extern __shared__ __align__(128) char smem[];
    const int tid = threadIdx.x;
    const int lane = tid & 31;
    const int wid = tid >> 5;
    const int wm = wid >> 2;       // 0..1  (M)
    const int wn = wid & 3;        // 0..3  (N)
    const int bx = blockIdx.x;     // N tile
    const int by = blockIdx.y;     // M tile

    const uint32_t sbase = smem_to_u32(smem);

    const __half* __restrict__ A = g_xh + (size_t)(by * BM) * DIM;
    const __half* __restrict__ B = g_yh + (size_t)(bx * BN) * DIM;

    // per-thread load mapping: 512 16B-chunks per matrix, 2 per thread
    const int c0row = tid >> 2;          // rows 0..63 (i=0), 64..127 (i=1)
    const int c0ch  = tid & 3;

    auto load_stage = [&](int sidx, int kt) {
        const uint32_t sb = sbase + sidx * STAGE;
        const int k0 = kt * BK;
        #pragma unroll
        for (int i = 0; i < 2; i++) {
            int row = c0row + i * 64;
            uint32_t so = SWZ_OFF(row, c0ch);
            size_t go = (size_t)row * DIM + k0 + c0ch * 8;
            cp_async16(sb + OFF_A + so, A + go);
            cp_async16(sb + OFF_B + so, B + go);
        }
        asm volatile("cp.async.commit_group;" ::: "memory");
    };

    float acc[4][4][4];
    #pragma unroll
    for (int i = 0; i < 4; i++)
        #pragma unroll
        for (int j = 0; j < 4; j++)
            #pragma unroll
            for (int k = 0; k < 4; k++) acc[i][j][k] = 0.0f;

    load_stage(0, 0);
    load_stage(1, 1);
    load_stage(2, 2);

    // ldmatrix row/chunk mapping
    const int arow = wm * 64 + (lane & 15);   // + mi*16
    const int brow = wn * 32 + (lane & 15);   // + nj*16
    const int chi  = lane >> 4;               // 0 or 1

    for (int kt = 0; kt < NKT; kt++) {
        if (kt + 2 < NKT)
            asm volatile("cp.async.wait_group 2;" ::: "memory");
        else if (kt + 1 < NKT)
            asm volatile("cp.async.wait_group 1;" ::: "memory");
        else
            asm volatile("cp.async.wait_group 0;" ::: "memory");
        __syncthreads();

        // refill the buffer consumed at kt-1 (sync above makes it safe)
        if (kt + 3 < NKT) load_stage((kt + 3) % NSTG, kt + 3);

        const uint32_t sb = sbase + (kt % NSTG) * STAGE;
        const uint32_t sA = sb + OFF_A;
        const uint32_t sB = sb + OFF_B;

        #pragma unroll
        for (int ks = 0; ks < 2; ks++) {
            const int ch = ks * 2 + chi;     // chunk index 0..3

            uint32_t a[4][4];
            #pragma unroll
            for (int mi = 0; mi < 4; mi++) {
                uint32_t ro = SWZ_OFF(arow + mi * 16, ch);
                ldsm_x4(a[mi][0], a[mi][1], a[mi][2], a[mi][3], sA + ro);
            }
            uint32_t b[2][4];
            #pragma unroll
            for (int nj = 0; nj < 2; nj++) {
                uint32_t ro = SWZ_OFF(brow + nj * 16, ch);
                ldsm_x4(b[nj][0], b[nj][1], b[nj][2], b[nj][3], sB + ro);
            }

            #pragma unroll
            for (int mi = 0; mi < 4; mi++) {
                #pragma unroll
                for (int nt = 0; nt < 4; nt++) {
                    const int nj = nt >> 1, h = nt & 1;
                    mma16816(acc[mi][nt], a[mi], b[nj][h], b[nj][h + 2]);
                }
            }
        }
    }

    // epilogue: scale by 20, direct float2 stores
    const int erow = by * BM + wm * 64 + (lane >> 2);
    const int ecol = bx * BN + wn * 32 + (lane & 3) * 2;
    #pragma unroll
    for (int mi = 0; mi < 4; mi++) {
        #pragma unroll
        for (int nt = 0; nt < 4; nt++) {
            float* p0 = C + (size_t)(erow + mi * 16) * NROWS + ecol + nt * 8;
            float* p1 = p0 + 8 * NROWS;
            *(float2*)p0 = make_float2(acc[mi][nt][0] * TEMP_INV,
                                       acc[mi][nt][1] * TEMP_INV);
            *(float2*)p1 = make_float2(acc[mi][nt][2] * TEMP_INV,
                                       acc[mi][nt][3] * TEMP_INV);
        }
    }
}

extern "C" void kernel_launch(void* const* d_in, const int* in_sizes, int n_in,
                              void* d_out, int out_size) {
    const float* x = (const float*)d_in[0];
    const float* y = (const float*)d_in[1];
    float* out = (float*)d_out;

    normalize_kernel<<<2 * NROWS, 256>>>(x, y);

    cudaFuncSetAttribute(gemm_hmma,
                         cudaFuncAttributeMaxDynamicSharedMemorySize, SMEM_TOTAL);
    dim3 grid(NROWS / BN, NROWS / BM);
    gemm_hmma<<<grid, 256, SMEM_TOTAL>>>(out);
}